// round 1
// baseline (speedup 1.0000x reference)
#include <cuda_runtime.h>
#include <cuda_bf16.h>
#include <math.h>

#define NB   2
#define CH   64
#define HT   128
#define WD   128
#define HW   16384
#define C3   192
#define C4   256

// ---------------- scratch (device globals; no allocation allowed) ----------
__device__ float g_qkv[NB * HW * C3];   // 24 MB  [token][192] (q scaled)
__device__ float g_aout[NB * HW * CH];  //  8 MB  attention output, token-major
__device__ float g_x2[NB * HW * CH];    //  8 MB  residual 1
__device__ float g_y1[NB * HW * C4];    // 32 MB  gelu(fc1)

__device__ __forceinline__ float warp_sum(float v) {
#pragma unroll
    for (int o = 16; o; o >>= 1) v += __shfl_xor_sync(0xffffffffu, v, o);
    return v;
}
__device__ __forceinline__ float warp_max(float v) {
#pragma unroll
    for (int o = 16; o; o >>= 1) v = fmaxf(v, __shfl_xor_sync(0xffffffffu, v, o));
    return v;
}

// ============================================================================
// K1: NCHW->token transpose + LayerNorm1 + QKV GEMM (192 outs), q pre-scaled.
// Block: 256 thr, 64 consecutive tokens. Warp = 8 tokens register-blocked.
// ============================================================================
__global__ __launch_bounds__(256, 1) void k_ln_qkv(
    const float* __restrict__ x, const float* __restrict__ qkv_w,
    const float* __restrict__ qkv_b, const float* __restrict__ ln_w,
    const float* __restrict__ ln_b)
{
    extern __shared__ float sm[];
    float* xs = sm;                 // [64][65]  raw x, channel-major
    float* xn = xs + 64 * 65;       // [64][68]  normalized, k-major (float4 rows)
    float* wT = xn + 64 * 68;       // [64][193] qkv_w transposed, pad 193
    float* bs = wT + 64 * 193;      // [192]
    float* ms = bs + 192;           // [64]
    float* rs = ms + 64;            // [64]

    const int tid = threadIdx.x;
    const int n = blockIdx.x >> 8;
    const int hw0 = (blockIdx.x & 255) << 6;
    const float* xin = x + (size_t)n * CH * HW + hw0;

    for (int idx = tid; idx < 64 * 64; idx += 256) {
        int c = idx >> 6, t = idx & 63;
        xs[c * 65 + t] = xin[(size_t)c * HW + t];
    }
    for (int idx = tid; idx < C3 * 64; idx += 256) {
        int o = idx >> 6, k = idx & 63;
        wT[k * 193 + o] = qkv_w[idx];
    }
    if (tid < C3) bs[tid] = qkv_b[tid];
    __syncthreads();

    const int warp = tid >> 5, lane = tid & 31;
    for (int j = 0; j < 8; j++) {
        int t = warp * 8 + j;
        float v0 = xs[(2 * lane) * 65 + t];
        float v1 = xs[(2 * lane + 1) * 65 + t];
        float s  = warp_sum(v0 + v1);
        float sq = warp_sum(v0 * v0 + v1 * v1);
        if (lane == 0) {
            float m = s * (1.0f / 64.0f);
            ms[t] = m;
            rs[t] = rsqrtf(sq * (1.0f / 64.0f) - m * m + 1e-5f);
        }
    }
    __syncthreads();
    for (int idx = tid; idx < 64 * 64; idx += 256) {
        int k = idx >> 6, t = idx & 63;
        xn[k * 68 + t] = (xs[k * 65 + t] - ms[t]) * rs[t] * ln_w[k] + ln_b[k];
    }
    __syncthreads();

    const int t0 = warp * 8;
    float acc[8][6];
#pragma unroll
    for (int jj = 0; jj < 6; jj++) {
        float b = bs[lane + 32 * jj];
#pragma unroll
        for (int t = 0; t < 8; t++) acc[t][jj] = b;
    }
#pragma unroll 4
    for (int k = 0; k < 64; k++) {
        float4 xa = *(const float4*)&xn[k * 68 + t0];
        float4 xb = *(const float4*)&xn[k * 68 + t0 + 4];
        float xv[8] = {xa.x, xa.y, xa.z, xa.w, xb.x, xb.y, xb.z, xb.w};
#pragma unroll
        for (int jj = 0; jj < 6; jj++) {
            float wv = wT[k * 193 + lane + 32 * jj];
#pragma unroll
            for (int t = 0; t < 8; t++) acc[t][jj] = fmaf(xv[t], wv, acc[t][jj]);
        }
    }
    float* qout = g_qkv + ((size_t)n * HW + hw0 + t0) * C3;
#pragma unroll
    for (int t = 0; t < 8; t++) {
#pragma unroll
        for (int jj = 0; jj < 6; jj++) {
            float v = acc[t][jj];
            if (jj < 2) v *= 0.17677669529663687f;  // dh^-0.5, dh=32
            qout[(size_t)t * C3 + lane + 32 * jj] = v;
        }
    }
}

// ============================================================================
// K2: neighborhood attention. Block = 8x8 query tile, one (n,head).
// Union K/V tile is 14x14 tokens x 32 dims in smem (row stride 33).
// Warp = one query row (8 queries): lanes->neighbors for scores/softmax,
// lanes->dims for the AV product.
// ============================================================================
__global__ __launch_bounds__(256, 1) void k_attn(const float* __restrict__ rpb)
{
    extern __shared__ float sm[];
    float* kx = sm;                  // [196][33]
    float* vx = kx + 196 * 33;       // [196][33]
    float* qx = vx + 196 * 33;       // [64][32]
    float* rp = qx + 64 * 32;        // [169]
    float* at = rp + 172;            // [8][52]

    const int tid = threadIdx.x, warp = tid >> 5, lane = tid & 31;
    const int b = blockIdx.x;
    const int nz = b >> 8, tile = b & 255;
    const int n = nz >> 1, z = nz & 1;
    const int h0 = (tile >> 4) << 3, w0 = (tile & 15) << 3;
    int r0 = h0 - 3; r0 = r0 < 0 ? 0 : (r0 > HT - 14 ? HT - 14 : r0);
    int c0 = w0 - 3; c0 = c0 < 0 ? 0 : (c0 > WD - 14 ? WD - 14 : c0);

    const float* qbase = g_qkv + (size_t)n * HW * C3;
    for (int rr = warp; rr < 196; rr += 8) {
        int pr = rr / 14, pc = rr - pr * 14;
        const float* p = qbase + (size_t)((r0 + pr) * WD + c0 + pc) * C3 + 64 + z * 32;
        kx[rr * 33 + lane] = p[lane];
        vx[rr * 33 + lane] = p[64 + lane];
    }
    for (int qi = warp; qi < 64; qi += 8) {
        int qh = h0 + (qi >> 3), qw = w0 + (qi & 7);
        qx[qi * 32 + lane] = qbase[(size_t)(qh * WD + qw) * C3 + z * 32 + lane];
    }
    if (tid < 169) rp[tid] = rpb[z * 169 + tid];
    __syncthreads();

    for (int j = 0; j < 8; j++) {
        const int qi = warp * 8 + j;
        const int qh = h0 + (qi >> 3), qw = w0 + (qi & 7);
        int sh = qh - 3; sh = sh < 0 ? 0 : (sh > HT - 7 ? HT - 7 : sh);
        int sw = qw - 3; sw = sw < 0 ? 0 : (sw > WD - 7 ? WD - 7 : sw);
        const int ph = sh - r0, pw = sw - c0;
        const int bh = qh - sh + 6, bw = qw - sw + 6;

        float s1, s2 = -1e30f;
        {
            int e = lane;
            int i = e / 7, jn = e - i * 7;
            const float* kr = &kx[((ph + i) * 14 + pw + jn) * 33];
            float s = rp[(bh - i) * 13 + (bw - jn)];
#pragma unroll
            for (int d4 = 0; d4 < 8; d4++) {
                float4 q4 = *(const float4*)&qx[qi * 32 + d4 * 4];
                s = fmaf(q4.x, kr[d4 * 4 + 0], s);
                s = fmaf(q4.y, kr[d4 * 4 + 1], s);
                s = fmaf(q4.z, kr[d4 * 4 + 2], s);
                s = fmaf(q4.w, kr[d4 * 4 + 3], s);
            }
            s1 = s;
        }
        if (lane < 17) {
            int e = lane + 32;
            int i = e / 7, jn = e - i * 7;
            const float* kr = &kx[((ph + i) * 14 + pw + jn) * 33];
            float s = rp[(bh - i) * 13 + (bw - jn)];
#pragma unroll
            for (int d4 = 0; d4 < 8; d4++) {
                float4 q4 = *(const float4*)&qx[qi * 32 + d4 * 4];
                s = fmaf(q4.x, kr[d4 * 4 + 0], s);
                s = fmaf(q4.y, kr[d4 * 4 + 1], s);
                s = fmaf(q4.z, kr[d4 * 4 + 2], s);
                s = fmaf(q4.w, kr[d4 * 4 + 3], s);
            }
            s2 = s;
        }
        float mx = warp_max(fmaxf(s1, s2));
        float p1 = __expf(s1 - mx);
        float p2 = (lane < 17) ? __expf(s2 - mx) : 0.0f;
        float inv = 1.0f / warp_sum(p1 + p2);
        at[warp * 52 + lane] = p1 * inv;
        if (lane < 17) at[warp * 52 + 32 + lane] = p2 * inv;
        __syncwarp();

        float o = 0.0f;
#pragma unroll
        for (int e = 0; e < 49; e++) {
            int i = e / 7, jn = e - i * 7;
            o = fmaf(at[warp * 52 + e], vx[((ph + i) * 14 + pw + jn) * 33 + lane], o);
        }
        g_aout[(size_t)(n * HW + qh * WD + qw) * CH + z * 32 + lane] = o;
        __syncwarp();
    }
}

// ============================================================================
// K3: proj GEMM + residual (shortcut read straight from NCHW x) -> g_x2
// ============================================================================
__global__ __launch_bounds__(256, 1) void k_proj(
    const float* __restrict__ x, const float* __restrict__ proj_w,
    const float* __restrict__ proj_b)
{
    extern __shared__ float sm[];
    float* as_ = sm;                // [64][68] attn out, k-major
    float* xs  = as_ + 64 * 68;     // [64][65] shortcut, channel-major
    float* wT  = xs + 64 * 65;      // [64][65]
    float* bs  = wT + 64 * 65;      // [64]

    const int tid = threadIdx.x;
    const int n = blockIdx.x >> 8, hw0 = (blockIdx.x & 255) << 6;
    const float* ain = g_aout + ((size_t)n * HW + hw0) * CH;
    for (int idx = tid; idx < 64 * 64; idx += 256) {
        int t = idx >> 6, k = idx & 63;
        as_[k * 68 + t] = ain[(size_t)t * CH + k];
    }
    const float* xin = x + (size_t)n * CH * HW + hw0;
    for (int idx = tid; idx < 64 * 64; idx += 256) {
        int c = idx >> 6, t = idx & 63;
        xs[c * 65 + t] = xin[(size_t)c * HW + t];
    }
    for (int idx = tid; idx < 64 * 64; idx += 256) {
        int c = idx >> 6, k = idx & 63;
        wT[k * 65 + c] = proj_w[idx];
    }
    if (tid < 64) bs[tid] = proj_b[tid];
    __syncthreads();

    const int warp = tid >> 5, lane = tid & 31, t0 = warp * 8;
    float acc0[8], acc1[8];
#pragma unroll
    for (int t = 0; t < 8; t++) { acc0[t] = bs[lane]; acc1[t] = bs[lane + 32]; }
#pragma unroll 4
    for (int k = 0; k < 64; k++) {
        float4 xa = *(const float4*)&as_[k * 68 + t0];
        float4 xb = *(const float4*)&as_[k * 68 + t0 + 4];
        float xv[8] = {xa.x, xa.y, xa.z, xa.w, xb.x, xb.y, xb.z, xb.w};
        float w0v = wT[k * 65 + lane], w1v = wT[k * 65 + lane + 32];
#pragma unroll
        for (int t = 0; t < 8; t++) {
            acc0[t] = fmaf(xv[t], w0v, acc0[t]);
            acc1[t] = fmaf(xv[t], w1v, acc1[t]);
        }
    }
    float* x2o = g_x2 + ((size_t)n * HW + hw0 + t0) * CH;
#pragma unroll
    for (int t = 0; t < 8; t++) {
        x2o[(size_t)t * CH + lane]      = acc0[t] + xs[lane * 65 + t0 + t];
        x2o[(size_t)t * CH + lane + 32] = acc1[t] + xs[(lane + 32) * 65 + t0 + t];
    }
}

// ============================================================================
// K4: LayerNorm2 + FC1 (64->256) + exact GELU -> g_y1
// ============================================================================
__global__ __launch_bounds__(256, 1) void k_ln_fc1(
    const float* __restrict__ fc1_w, const float* __restrict__ fc1_b,
    const float* __restrict__ ln_w, const float* __restrict__ ln_b)
{
    extern __shared__ float sm[];
    float* xs = sm;                 // [64][68] x2 k-major (normalized in place)
    float* wT = xs + 64 * 68;       // [64][257]
    float* bs = wT + 64 * 257;      // [256]
    float* ms = bs + 256;           // [64]
    float* rs = ms + 64;            // [64]

    const int tid = threadIdx.x;
    const int n = blockIdx.x >> 8, hw0 = (blockIdx.x & 255) << 6;
    const float* xin = g_x2 + ((size_t)n * HW + hw0) * CH;
    for (int idx = tid; idx < 64 * 64; idx += 256) {
        int t = idx >> 6, k = idx & 63;
        xs[k * 68 + t] = xin[(size_t)t * CH + k];
    }
    for (int idx = tid; idx < C4 * 64; idx += 256) {
        int o = idx >> 6, k = idx & 63;
        wT[k * 257 + o] = fc1_w[idx];
    }
    if (tid < C4) bs[tid] = fc1_b[tid];
    __syncthreads();

    const int warp = tid >> 5, lane = tid & 31;
    for (int j = 0; j < 8; j++) {
        int t = warp * 8 + j;
        float v0 = xs[(2 * lane) * 68 + t];
        float v1 = xs[(2 * lane + 1) * 68 + t];
        float s  = warp_sum(v0 + v1);
        float sq = warp_sum(v0 * v0 + v1 * v1);
        if (lane == 0) {
            float m = s * (1.0f / 64.0f);
            ms[t] = m;
            rs[t] = rsqrtf(sq * (1.0f / 64.0f) - m * m + 1e-5f);
        }
    }
    __syncthreads();
    for (int idx = tid; idx < 64 * 64; idx += 256) {
        int k = idx >> 6, t = idx & 63;
        xs[k * 68 + t] = (xs[k * 68 + t] - ms[t]) * rs[t] * ln_w[k] + ln_b[k];
    }
    __syncthreads();

    const int t0 = warp * 8;
    float acc[8][8];
#pragma unroll
    for (int jj = 0; jj < 8; jj++) {
        float b = bs[lane + 32 * jj];
#pragma unroll
        for (int t = 0; t < 8; t++) acc[t][jj] = b;
    }
#pragma unroll 2
    for (int k = 0; k < 64; k++) {
        float4 xa = *(const float4*)&xs[k * 68 + t0];
        float4 xb = *(const float4*)&xs[k * 68 + t0 + 4];
        float xv[8] = {xa.x, xa.y, xa.z, xa.w, xb.x, xb.y, xb.z, xb.w};
#pragma unroll
        for (int jj = 0; jj < 8; jj++) {
            float wv = wT[k * 257 + lane + 32 * jj];
#pragma unroll
            for (int t = 0; t < 8; t++) acc[t][jj] = fmaf(xv[t], wv, acc[t][jj]);
        }
    }
    float* yo = g_y1 + ((size_t)n * HW + hw0 + t0) * C4;
#pragma unroll
    for (int t = 0; t < 8; t++) {
#pragma unroll
        for (int jj = 0; jj < 8; jj++) {
            float v = acc[t][jj];
            v = 0.5f * v * (1.0f + erff(v * 0.70710678118654752f));
            yo[(size_t)t * C4 + lane + 32 * jj] = v;
        }
    }
}

// ============================================================================
// K5: FC2 (256->64) + residual + token-major -> NCHW transposed store
// ============================================================================
__global__ __launch_bounds__(256, 1) void k_fc2(
    const float* __restrict__ fc2_w, const float* __restrict__ fc2_b,
    float* __restrict__ out)
{
    extern __shared__ float sm[];
    float* ys = sm;                  // [256][68]
    float* wT = ys + 256 * 68;       // [256][65]
    float* os = wT + 256 * 65;       // [64][68]
    float* bs = os + 64 * 68;        // [64]

    const int tid = threadIdx.x;
    const int n = blockIdx.x >> 8, hw0 = (blockIdx.x & 255) << 6;
    const float* yin = g_y1 + ((size_t)n * HW + hw0) * C4;
    for (int idx = tid; idx < 64 * 256; idx += 256) {
        int t = idx >> 8, k = idx & 255;
        ys[k * 68 + t] = yin[(size_t)t * C4 + k];
    }
    for (int idx = tid; idx < 64 * 256; idx += 256) {
        int c = idx >> 8, k = idx & 255;
        wT[k * 65 + c] = fc2_w[idx];
    }
    if (tid < 64) bs[tid] = fc2_b[tid];
    __syncthreads();

    const int warp = tid >> 5, lane = tid & 31, t0 = warp * 8;
    float acc0[8], acc1[8];
#pragma unroll
    for (int t = 0; t < 8; t++) { acc0[t] = bs[lane]; acc1[t] = bs[lane + 32]; }
#pragma unroll 4
    for (int k = 0; k < 256; k++) {
        float4 xa = *(const float4*)&ys[k * 68 + t0];
        float4 xb = *(const float4*)&ys[k * 68 + t0 + 4];
        float xv[8] = {xa.x, xa.y, xa.z, xa.w, xb.x, xb.y, xb.z, xb.w};
        float w0v = wT[k * 65 + lane], w1v = wT[k * 65 + lane + 32];
#pragma unroll
        for (int t = 0; t < 8; t++) {
            acc0[t] = fmaf(xv[t], w0v, acc0[t]);
            acc1[t] = fmaf(xv[t], w1v, acc1[t]);
        }
    }
    const float* x2in = g_x2 + ((size_t)n * HW + hw0 + t0) * CH;
#pragma unroll
    for (int t = 0; t < 8; t++) {
        os[lane * 68 + t0 + t]        = acc0[t] + x2in[(size_t)t * CH + lane];
        os[(lane + 32) * 68 + t0 + t] = acc1[t] + x2in[(size_t)t * CH + lane + 32];
    }
    __syncthreads();
    float* oo = out + (size_t)n * CH * HW + hw0;
    for (int idx = tid; idx < 64 * 64; idx += 256) {
        int c = idx >> 6, t = idx & 63;
        oo[(size_t)c * HW + t] = os[c * 68 + t];
    }
}

// ---------------------------------------------------------------------------
extern "C" void kernel_launch(void* const* d_in, const int* in_sizes, int n_in,
                              void* d_out, int out_size)
{
    const float* x      = (const float*)d_in[0];
    const float* qkv_w  = (const float*)d_in[1];
    const float* qkv_b  = (const float*)d_in[2];
    const float* proj_w = (const float*)d_in[3];
    const float* proj_b = (const float*)d_in[4];
    const float* rpb    = (const float*)d_in[5];
    const float* ln1_w  = (const float*)d_in[6];
    const float* ln1_b  = (const float*)d_in[7];
    const float* ln2_w  = (const float*)d_in[8];
    const float* ln2_b  = (const float*)d_in[9];
    const float* fc1_w  = (const float*)d_in[10];
    const float* fc1_b  = (const float*)d_in[11];
    const float* fc2_w  = (const float*)d_in[12];
    const float* fc2_b  = (const float*)d_in[13];
    float* out = (float*)d_out;

    const int smB = (64 * 65 + 64 * 68 + 64 * 193 + 192 + 64 + 64) * 4;
    const int smC = (196 * 33 * 2 + 64 * 32 + 172 + 8 * 52) * 4;
    const int smD = (64 * 68 + 64 * 65 + 64 * 65 + 64) * 4;
    const int smE = (64 * 68 + 64 * 257 + 256 + 64 + 64) * 4;
    const int smF = (256 * 68 + 256 * 65 + 64 * 68 + 64) * 4;

    cudaFuncSetAttribute(k_ln_qkv, cudaFuncAttributeMaxDynamicSharedMemorySize, smB);
    cudaFuncSetAttribute(k_attn,   cudaFuncAttributeMaxDynamicSharedMemorySize, smC);
    cudaFuncSetAttribute(k_proj,   cudaFuncAttributeMaxDynamicSharedMemorySize, smD);
    cudaFuncSetAttribute(k_ln_fc1, cudaFuncAttributeMaxDynamicSharedMemorySize, smE);
    cudaFuncSetAttribute(k_fc2,    cudaFuncAttributeMaxDynamicSharedMemorySize, smF);

    k_ln_qkv<<<512, 256, smB>>>(x, qkv_w, qkv_b, ln1_w, ln1_b);
    k_attn<<<1024, 256, smC>>>(rpb);
    k_proj<<<512, 256, smD>>>(x, proj_w, proj_b);
    k_ln_fc1<<<512, 256, smE>>>(fc1_w, fc1_b, ln2_w, ln2_b);
    k_fc2<<<512, 256, smF>>>(fc2_w, fc2_b, out);
}

// round 2
// speedup vs baseline: 1.1073x; 1.1073x over previous
#include <cuda_runtime.h>
#include <cuda_bf16.h>
#include <math.h>

#define NB   2
#define CH   64
#define HT   128
#define WD   128
#define HW   16384
#define C3   192
#define C4   256

typedef unsigned long long u64;

// ---------------- scratch (device globals; no allocation allowed) ----------
__device__ float g_qkv[NB * HW * C3];   // [token][192] (q scaled)
__device__ float g_aout[NB * HW * CH];  // attention output, token-major
__device__ float g_x2[NB * HW * CH];    // residual 1
__device__ float g_y1[NB * HW * C4];    // gelu(fc1)
__device__ float g_wt2[C4 * CH];        // fc2_w transposed [256][64]

__device__ __forceinline__ float warp_sum(float v) {
#pragma unroll
    for (int o = 16; o; o >>= 1) v += __shfl_xor_sync(0xffffffffu, v, o);
    return v;
}
__device__ __forceinline__ float warp_max(float v) {
#pragma unroll
    for (int o = 16; o; o >>= 1) v = fmaxf(v, __shfl_xor_sync(0xffffffffu, v, o));
    return v;
}
// packed fp32x2 helpers (sm_100+)
__device__ __forceinline__ u64 pk2(float v) {
    u64 r; asm("mov.b64 %0,{%1,%1};" : "=l"(r) : "f"(v)); return r;
}
__device__ __forceinline__ void fma2(u64& d, u64 a, u64 b) {
    asm("fma.rn.f32x2 %0,%1,%2,%0;" : "+l"(d) : "l"(a), "l"(b));
}
__device__ __forceinline__ float2 up2(u64 v) {
    float2 f; asm("mov.b64 {%0,%1},%2;" : "=f"(f.x), "=f"(f.y) : "l"(v)); return f;
}

// ============================================================================
// K0: transpose fc2_w [64][256] -> g_wt2 [256][64]
// ============================================================================
__global__ void k_wt(const float* __restrict__ w) {
    __shared__ float t[32][33];
    int k0 = (blockIdx.x & 7) * 32, c0 = (blockIdx.x >> 3) * 32;
    int lx = threadIdx.x & 31, ly = threadIdx.x >> 5;
    for (int i = ly; i < 32; i += 8) t[i][lx] = w[(c0 + i) * C4 + k0 + lx];
    __syncthreads();
    for (int i = ly; i < 32; i += 8) g_wt2[(k0 + i) * CH + c0 + lx] = t[lx][i];
}

// ============================================================================
// K1: NCHW->token transpose + LayerNorm1 + QKV GEMM (192 outs), q pre-scaled.
// 256 thr / 64 tokens; warp = 8 tokens (4 f32x2 pairs) x 6 output cols.
// ============================================================================
__global__ __launch_bounds__(256, 2) void k_ln_qkv(
    const float* __restrict__ x, const float* __restrict__ qkv_w,
    const float* __restrict__ qkv_b, const float* __restrict__ ln_w,
    const float* __restrict__ ln_b)
{
    extern __shared__ float sm[];
    float* xs = sm;                 // [64][65]
    float* xn = xs + 64 * 65;       // [64][68]
    float* wT = xn + 64 * 68;       // [64][193]
    float* bs = wT + 64 * 193;      // [192]
    float* ms = bs + 192;           // [64]
    float* rs = ms + 64;            // [64]

    const int tid = threadIdx.x;
    const int n = blockIdx.x >> 8;
    const int hw0 = (blockIdx.x & 255) << 6;
    const float* xin = x + (size_t)n * CH * HW + hw0;

    for (int idx = tid; idx < 64 * 64; idx += 256) {
        int c = idx >> 6, t = idx & 63;
        xs[c * 65 + t] = xin[(size_t)c * HW + t];
    }
    for (int idx = tid; idx < C3 * 64; idx += 256) {
        int o = idx >> 6, k = idx & 63;
        wT[k * 193 + o] = qkv_w[idx];
    }
    if (tid < C3) bs[tid] = qkv_b[tid];
    __syncthreads();

    const int warp = tid >> 5, lane = tid & 31;
    for (int j = 0; j < 8; j++) {
        int t = warp * 8 + j;
        float v0 = xs[(2 * lane) * 65 + t];
        float v1 = xs[(2 * lane + 1) * 65 + t];
        float s  = warp_sum(v0 + v1);
        float sq = warp_sum(v0 * v0 + v1 * v1);
        if (lane == 0) {
            float m = s * (1.0f / 64.0f);
            ms[t] = m;
            rs[t] = rsqrtf(sq * (1.0f / 64.0f) - m * m + 1e-5f);
        }
    }
    __syncthreads();
    for (int idx = tid; idx < 64 * 64; idx += 256) {
        int k = idx >> 6, t = idx & 63;
        xn[k * 68 + t] = (xs[k * 65 + t] - ms[t]) * rs[t] * ln_w[k] + ln_b[k];
    }
    __syncthreads();

    const int t0 = warp * 8;
    u64 acc[6][4];
#pragma unroll
    for (int jj = 0; jj < 6; jj++) {
        u64 b = pk2(bs[lane + 32 * jj]);
#pragma unroll
        for (int p = 0; p < 4; p++) acc[jj][p] = b;
    }
#pragma unroll 4
    for (int k = 0; k < 64; k++) {
        ulonglong2 xa = *(const ulonglong2*)&xn[k * 68 + t0];
        ulonglong2 xb = *(const ulonglong2*)&xn[k * 68 + t0 + 4];
#pragma unroll
        for (int jj = 0; jj < 6; jj++) {
            u64 w = pk2(wT[k * 193 + lane + 32 * jj]);
            fma2(acc[jj][0], xa.x, w);
            fma2(acc[jj][1], xa.y, w);
            fma2(acc[jj][2], xb.x, w);
            fma2(acc[jj][3], xb.y, w);
        }
    }
    float* qout = g_qkv + ((size_t)n * HW + hw0 + t0) * C3;
#pragma unroll
    for (int p = 0; p < 4; p++) {
#pragma unroll
        for (int jj = 0; jj < 6; jj++) {
            float2 v = up2(acc[jj][p]);
            if (jj < 2) { v.x *= 0.17677669529663687f; v.y *= 0.17677669529663687f; }
            qout[(size_t)(2 * p) * C3 + lane + 32 * jj]     = v.x;
            qout[(size_t)(2 * p + 1) * C3 + lane + 32 * jj] = v.y;
        }
    }
}

// ============================================================================
// K2: neighborhood attention (8x8 query tile per (n,head)).
// ============================================================================
__global__ __launch_bounds__(256, 2) void k_attn(const float* __restrict__ rpb)
{
    extern __shared__ float sm[];
    float* kx = sm;                  // [196][33]
    float* vx = kx + 196 * 33;       // [196][33]
    float* qx = vx + 196 * 33;       // [64][32]
    float* rp = qx + 64 * 32;        // [169]
    float* at = rp + 172;            // [8][52]

    const int tid = threadIdx.x, warp = tid >> 5, lane = tid & 31;
    const int b = blockIdx.x;
    const int nz = b >> 8, tile = b & 255;
    const int n = nz >> 1, z = nz & 1;
    const int h0 = (tile >> 4) << 3, w0 = (tile & 15) << 3;
    int r0 = h0 - 3; r0 = r0 < 0 ? 0 : (r0 > HT - 14 ? HT - 14 : r0);
    int c0 = w0 - 3; c0 = c0 < 0 ? 0 : (c0 > WD - 14 ? WD - 14 : c0);

    const float* qbase = g_qkv + (size_t)n * HW * C3;
    for (int rr = warp; rr < 196; rr += 8) {
        int pr = rr / 14, pc = rr - pr * 14;
        const float* p = qbase + (size_t)((r0 + pr) * WD + c0 + pc) * C3 + 64 + z * 32;
        kx[rr * 33 + lane] = p[lane];
        vx[rr * 33 + lane] = p[64 + lane];
    }
    for (int qi = warp; qi < 64; qi += 8) {
        int qh = h0 + (qi >> 3), qw = w0 + (qi & 7);
        qx[qi * 32 + lane] = qbase[(size_t)(qh * WD + qw) * C3 + z * 32 + lane];
    }
    if (tid < 169) rp[tid] = rpb[z * 169 + tid];
    __syncthreads();

    for (int j = 0; j < 8; j++) {
        const int qi = warp * 8 + j;
        const int qh = h0 + (qi >> 3), qw = w0 + (qi & 7);
        int sh = qh - 3; sh = sh < 0 ? 0 : (sh > HT - 7 ? HT - 7 : sh);
        int sw = qw - 3; sw = sw < 0 ? 0 : (sw > WD - 7 ? WD - 7 : sw);
        const int ph = sh - r0, pw = sw - c0;
        const int bh = qh - sh + 6, bw = qw - sw + 6;

        float4 q4[8];
#pragma unroll
        for (int d4 = 0; d4 < 8; d4++) q4[d4] = *(const float4*)&qx[qi * 32 + d4 * 4];

        float s1, s2 = -1e30f;
        {
            int e = lane;
            int i = e / 7, jn = e - i * 7;
            const float* kr = &kx[((ph + i) * 14 + pw + jn) * 33];
            float s = rp[(bh - i) * 13 + (bw - jn)];
#pragma unroll
            for (int d4 = 0; d4 < 8; d4++) {
                s = fmaf(q4[d4].x, kr[d4 * 4 + 0], s);
                s = fmaf(q4[d4].y, kr[d4 * 4 + 1], s);
                s = fmaf(q4[d4].z, kr[d4 * 4 + 2], s);
                s = fmaf(q4[d4].w, kr[d4 * 4 + 3], s);
            }
            s1 = s;
        }
        if (lane < 17) {
            int e = lane + 32;
            int i = e / 7, jn = e - i * 7;
            const float* kr = &kx[((ph + i) * 14 + pw + jn) * 33];
            float s = rp[(bh - i) * 13 + (bw - jn)];
#pragma unroll
            for (int d4 = 0; d4 < 8; d4++) {
                s = fmaf(q4[d4].x, kr[d4 * 4 + 0], s);
                s = fmaf(q4[d4].y, kr[d4 * 4 + 1], s);
                s = fmaf(q4[d4].z, kr[d4 * 4 + 2], s);
                s = fmaf(q4[d4].w, kr[d4 * 4 + 3], s);
            }
            s2 = s;
        }
        float mx = warp_max(fmaxf(s1, s2));
        float p1 = __expf(s1 - mx);
        float p2 = (lane < 17) ? __expf(s2 - mx) : 0.0f;
        float inv = 1.0f / warp_sum(p1 + p2);
        at[warp * 52 + lane] = p1 * inv;
        if (lane < 17) at[warp * 52 + 32 + lane] = p2 * inv;
        __syncwarp();

        float o = 0.0f;
#pragma unroll
        for (int e = 0; e < 49; e++) {
            int i = e / 7, jn = e - i * 7;
            o = fmaf(at[warp * 52 + e], vx[((ph + i) * 14 + pw + jn) * 33 + lane], o);
        }
        g_aout[(size_t)(n * HW + qh * WD + qw) * CH + z * 32 + lane] = o;
        __syncwarp();
    }
}

// ============================================================================
// K3: proj GEMM + residual -> g_x2  (f32x2: 4 token-pairs x 2 out cols)
// ============================================================================
__global__ __launch_bounds__(256, 2) void k_proj(
    const float* __restrict__ x, const float* __restrict__ proj_w,
    const float* __restrict__ proj_b)
{
    extern __shared__ float sm[];
    float* as_ = sm;                // [64][68]
    float* xs  = as_ + 64 * 68;     // [64][65]
    float* wT  = xs + 64 * 65;      // [64][65]
    float* bs  = wT + 64 * 65;      // [64]

    const int tid = threadIdx.x;
    const int n = blockIdx.x >> 8, hw0 = (blockIdx.x & 255) << 6;
    const float* ain = g_aout + ((size_t)n * HW + hw0) * CH;
    for (int idx = tid; idx < 64 * 64; idx += 256) {
        int t = idx >> 6, k = idx & 63;
        as_[k * 68 + t] = ain[(size_t)t * CH + k];
    }
    const float* xin = x + (size_t)n * CH * HW + hw0;
    for (int idx = tid; idx < 64 * 64; idx += 256) {
        int c = idx >> 6, t = idx & 63;
        xs[c * 65 + t] = xin[(size_t)c * HW + t];
    }
    for (int idx = tid; idx < 64 * 64; idx += 256) {
        int c = idx >> 6, k = idx & 63;
        wT[k * 65 + c] = proj_w[idx];
    }
    if (tid < 64) bs[tid] = proj_b[tid];
    __syncthreads();

    const int warp = tid >> 5, lane = tid & 31, t0 = warp * 8;
    u64 a0[4], a1[4];
    {
        u64 b0 = pk2(bs[lane]), b1 = pk2(bs[lane + 32]);
#pragma unroll
        for (int p = 0; p < 4; p++) { a0[p] = b0; a1[p] = b1; }
    }
#pragma unroll 4
    for (int k = 0; k < 64; k++) {
        ulonglong2 xa = *(const ulonglong2*)&as_[k * 68 + t0];
        ulonglong2 xb = *(const ulonglong2*)&as_[k * 68 + t0 + 4];
        u64 w0 = pk2(wT[k * 65 + lane]);
        u64 w1 = pk2(wT[k * 65 + lane + 32]);
        fma2(a0[0], xa.x, w0); fma2(a0[1], xa.y, w0);
        fma2(a0[2], xb.x, w0); fma2(a0[3], xb.y, w0);
        fma2(a1[0], xa.x, w1); fma2(a1[1], xa.y, w1);
        fma2(a1[2], xb.x, w1); fma2(a1[3], xb.y, w1);
    }
    float* x2o = g_x2 + ((size_t)n * HW + hw0 + t0) * CH;
#pragma unroll
    for (int p = 0; p < 4; p++) {
        float2 v0 = up2(a0[p]), v1 = up2(a1[p]);
        int t = 2 * p;
        x2o[(size_t)t * CH + lane]            = v0.x + xs[lane * 65 + t0 + t];
        x2o[(size_t)(t + 1) * CH + lane]      = v0.y + xs[lane * 65 + t0 + t + 1];
        x2o[(size_t)t * CH + lane + 32]       = v1.x + xs[(lane + 32) * 65 + t0 + t];
        x2o[(size_t)(t + 1) * CH + lane + 32] = v1.y + xs[(lane + 32) * 65 + t0 + t + 1];
    }
}

// ============================================================================
// K4: LayerNorm2 + FC1 (64->256) + exact GELU -> g_y1 (f32x2)
// ============================================================================
__global__ __launch_bounds__(256, 2) void k_ln_fc1(
    const float* __restrict__ fc1_w, const float* __restrict__ fc1_b,
    const float* __restrict__ ln_w, const float* __restrict__ ln_b)
{
    extern __shared__ float sm[];
    float* xs = sm;                 // [64][68]
    float* wT = xs + 64 * 68;       // [64][257]
    float* bs = wT + 64 * 257;      // [256]
    float* ms = bs + 256;           // [64]
    float* rs = ms + 64;            // [64]

    const int tid = threadIdx.x;
    const int n = blockIdx.x >> 8, hw0 = (blockIdx.x & 255) << 6;
    const float* xin = g_x2 + ((size_t)n * HW + hw0) * CH;
    for (int idx = tid; idx < 64 * 64; idx += 256) {
        int t = idx >> 6, k = idx & 63;
        xs[k * 68 + t] = xin[(size_t)t * CH + k];
    }
    for (int idx = tid; idx < C4 * 64; idx += 256) {
        int o = idx >> 6, k = idx & 63;
        wT[k * 257 + o] = fc1_w[idx];
    }
    if (tid < C4) bs[tid] = fc1_b[tid];
    __syncthreads();

    const int warp = tid >> 5, lane = tid & 31;
    for (int j = 0; j < 8; j++) {
        int t = warp * 8 + j;
        float v0 = xs[(2 * lane) * 68 + t];
        float v1 = xs[(2 * lane + 1) * 68 + t];
        float s  = warp_sum(v0 + v1);
        float sq = warp_sum(v0 * v0 + v1 * v1);
        if (lane == 0) {
            float m = s * (1.0f / 64.0f);
            ms[t] = m;
            rs[t] = rsqrtf(sq * (1.0f / 64.0f) - m * m + 1e-5f);
        }
    }
    __syncthreads();
    for (int idx = tid; idx < 64 * 64; idx += 256) {
        int k = idx >> 6, t = idx & 63;
        xs[k * 68 + t] = (xs[k * 68 + t] - ms[t]) * rs[t] * ln_w[k] + ln_b[k];
    }
    __syncthreads();

    const int t0 = warp * 8;
    u64 acc[8][4];
#pragma unroll
    for (int jj = 0; jj < 8; jj++) {
        u64 b = pk2(bs[lane + 32 * jj]);
#pragma unroll
        for (int p = 0; p < 4; p++) acc[jj][p] = b;
    }
#pragma unroll 2
    for (int k = 0; k < 64; k++) {
        ulonglong2 xa = *(const ulonglong2*)&xs[k * 68 + t0];
        ulonglong2 xb = *(const ulonglong2*)&xs[k * 68 + t0 + 4];
#pragma unroll
        for (int jj = 0; jj < 8; jj++) {
            u64 w = pk2(wT[k * 257 + lane + 32 * jj]);
            fma2(acc[jj][0], xa.x, w);
            fma2(acc[jj][1], xa.y, w);
            fma2(acc[jj][2], xb.x, w);
            fma2(acc[jj][3], xb.y, w);
        }
    }
    float* yo = g_y1 + ((size_t)n * HW + hw0 + t0) * C4;
#pragma unroll
    for (int p = 0; p < 4; p++) {
#pragma unroll
        for (int jj = 0; jj < 8; jj++) {
            float2 v = up2(acc[jj][p]);
            v.x = 0.5f * v.x * (1.0f + erff(v.x * 0.70710678118654752f));
            v.y = 0.5f * v.y * (1.0f + erff(v.y * 0.70710678118654752f));
            yo[(size_t)(2 * p) * C4 + lane + 32 * jj]     = v.x;
            yo[(size_t)(2 * p + 1) * C4 + lane + 32 * jj] = v.y;
        }
    }
}

// ============================================================================
// K5: FC2 (256->64) + residual + NHWC->NCHW store (f32x2, weights via LDG)
// ============================================================================
__global__ __launch_bounds__(256, 2) void k_fc2(
    const float* __restrict__ fc2_b, float* __restrict__ out)
{
    extern __shared__ float sm[];
    float* ys = sm;                  // [256][68]
    float* os = ys + 256 * 68;       // [64][68]
    float* bs = os + 64 * 68;        // [64]

    const int tid = threadIdx.x;
    const int n = blockIdx.x >> 8, hw0 = (blockIdx.x & 255) << 6;
    const float* yin = g_y1 + ((size_t)n * HW + hw0) * C4;
    for (int idx = tid; idx < 64 * 256; idx += 256) {
        int t = idx >> 8, k = idx & 255;
        ys[k * 68 + t] = yin[(size_t)t * C4 + k];
    }
    if (tid < 64) bs[tid] = fc2_b[tid];
    __syncthreads();

    const int warp = tid >> 5, lane = tid & 31, t0 = warp * 8;
    u64 a0[4], a1[4];
    {
        u64 b0 = pk2(bs[lane]), b1 = pk2(bs[lane + 32]);
#pragma unroll
        for (int p = 0; p < 4; p++) { a0[p] = b0; a1[p] = b1; }
    }
#pragma unroll 4
    for (int k = 0; k < 256; k++) {
        ulonglong2 xa = *(const ulonglong2*)&ys[k * 68 + t0];
        ulonglong2 xb = *(const ulonglong2*)&ys[k * 68 + t0 + 4];
        u64 w0 = pk2(__ldg(&g_wt2[k * CH + lane]));
        u64 w1 = pk2(__ldg(&g_wt2[k * CH + lane + 32]));
        fma2(a0[0], xa.x, w0); fma2(a0[1], xa.y, w0);
        fma2(a0[2], xb.x, w0); fma2(a0[3], xb.y, w0);
        fma2(a1[0], xa.x, w1); fma2(a1[1], xa.y, w1);
        fma2(a1[2], xb.x, w1); fma2(a1[3], xb.y, w1);
    }
    const float* x2in = g_x2 + ((size_t)n * HW + hw0 + t0) * CH;
#pragma unroll
    for (int p = 0; p < 4; p++) {
        float2 v0 = up2(a0[p]), v1 = up2(a1[p]);
        int t = 2 * p;
        os[lane * 68 + t0 + t]            = v0.x + x2in[(size_t)t * CH + lane];
        os[lane * 68 + t0 + t + 1]        = v0.y + x2in[(size_t)(t + 1) * CH + lane];
        os[(lane + 32) * 68 + t0 + t]     = v1.x + x2in[(size_t)t * CH + lane + 32];
        os[(lane + 32) * 68 + t0 + t + 1] = v1.y + x2in[(size_t)(t + 1) * CH + lane + 32];
    }
    __syncthreads();
    float* oo = out + (size_t)n * CH * HW + hw0;
    for (int idx = tid; idx < 64 * 64; idx += 256) {
        int c = idx >> 6, t = idx & 63;
        oo[(size_t)c * HW + t] = os[c * 68 + t];
    }
}

// ---------------------------------------------------------------------------
extern "C" void kernel_launch(void* const* d_in, const int* in_sizes, int n_in,
                              void* d_out, int out_size)
{
    const float* x      = (const float*)d_in[0];
    const float* qkv_w  = (const float*)d_in[1];
    const float* qkv_b  = (const float*)d_in[2];
    const float* proj_w = (const float*)d_in[3];
    const float* proj_b = (const float*)d_in[4];
    const float* rpb    = (const float*)d_in[5];
    const float* ln1_w  = (const float*)d_in[6];
    const float* ln1_b  = (const float*)d_in[7];
    const float* ln2_w  = (const float*)d_in[8];
    const float* ln2_b  = (const float*)d_in[9];
    const float* fc1_w  = (const float*)d_in[10];
    const float* fc1_b  = (const float*)d_in[11];
    const float* fc2_w  = (const float*)d_in[12];
    const float* fc2_b  = (const float*)d_in[13];
    float* out = (float*)d_out;

    const int smB = (64 * 65 + 64 * 68 + 64 * 193 + 192 + 64 + 64) * 4;
    const int smC = (196 * 33 * 2 + 64 * 32 + 172 + 8 * 52) * 4;
    const int smD = (64 * 68 + 64 * 65 + 64 * 65 + 64) * 4;
    const int smE = (64 * 68 + 64 * 257 + 256 + 64 + 64) * 4;
    const int smF = (256 * 68 + 64 * 68 + 64) * 4;

    cudaFuncSetAttribute(k_ln_qkv, cudaFuncAttributeMaxDynamicSharedMemorySize, smB);
    cudaFuncSetAttribute(k_attn,   cudaFuncAttributeMaxDynamicSharedMemorySize, smC);
    cudaFuncSetAttribute(k_proj,   cudaFuncAttributeMaxDynamicSharedMemorySize, smD);
    cudaFuncSetAttribute(k_ln_fc1, cudaFuncAttributeMaxDynamicSharedMemorySize, smE);
    cudaFuncSetAttribute(k_fc2,    cudaFuncAttributeMaxDynamicSharedMemorySize, smF);

    k_wt<<<16, 256>>>(fc2_w);
    k_ln_qkv<<<512, 256, smB>>>(x, qkv_w, qkv_b, ln1_w, ln1_b);
    k_attn<<<1024, 256, smC>>>(rpb);
    k_proj<<<512, 256, smD>>>(x, proj_w, proj_b);
    k_ln_fc1<<<512, 256, smE>>>(fc1_w, fc1_b, ln2_w, ln2_b);
    k_fc2<<<512, 256, smF>>>(fc2_b, out);
}

// round 3
// speedup vs baseline: 1.3079x; 1.1811x over previous
#include <cuda_runtime.h>
#include <cuda_bf16.h>
#include <math.h>

#define NB   2
#define CH   64
#define HT   128
#define WD   128
#define HW   16384
#define C3   192
#define C4   256

typedef unsigned long long u64;

// ---------------- scratch (device globals; no allocation allowed) ----------
__device__ float g_qkv[NB * HW * C3];   // [token][192] (q scaled)
__device__ float g_aout[NB * HW * CH];  // attention output, token-major
__device__ float g_wt2d[C4 * 2 * CH];   // fc2_w transposed + duplicated pairs [256][128]

__device__ __forceinline__ float warp_sum(float v) {
#pragma unroll
    for (int o = 16; o; o >>= 1) v += __shfl_xor_sync(0xffffffffu, v, o);
    return v;
}
__device__ __forceinline__ float warp_max(float v) {
#pragma unroll
    for (int o = 16; o; o >>= 1) v = fmaxf(v, __shfl_xor_sync(0xffffffffu, v, o));
    return v;
}
// packed fp32x2 helpers (sm_100+)
__device__ __forceinline__ u64 pk2(float v) {
    u64 r; asm("mov.b64 %0,{%1,%1};" : "=l"(r) : "f"(v)); return r;
}
__device__ __forceinline__ void fma2(u64& d, u64 a, u64 b) {
    asm("fma.rn.f32x2 %0,%1,%2,%0;" : "+l"(d) : "l"(a), "l"(b));
}
__device__ __forceinline__ float2 up2(u64 v) {
    float2 f; asm("mov.b64 {%0,%1},%2;" : "=f"(f.x), "=f"(f.y) : "l"(v)); return f;
}

// ============================================================================
// K0: fc2_w [64][256] -> g_wt2d [256][2*64] duplicated-packed
// ============================================================================
__global__ void k_wt(const float* __restrict__ w) {
    int i = blockIdx.x * 256 + threadIdx.x;      // [0, 64*256)
    int c = i >> 8, k = i & 255;
    float v = w[i];
    g_wt2d[k * 128 + 2 * c]     = v;
    g_wt2d[k * 128 + 2 * c + 1] = v;
}

// ============================================================================
// K1: NCHW->token transpose + LayerNorm1 + QKV GEMM (192 outs), q pre-scaled.
// ============================================================================
__global__ __launch_bounds__(256, 2) void k_ln_qkv(
    const float* __restrict__ x, const float* __restrict__ qkv_w,
    const float* __restrict__ qkv_b, const float* __restrict__ ln_w,
    const float* __restrict__ ln_b)
{
    extern __shared__ float sm[];
    float* xs = sm;                 // [64][65]
    float* xn = xs + 64 * 65;       // [64][68]
    float* wT = xn + 64 * 68;       // [64][193]
    float* bs = wT + 64 * 193;      // [192]
    float* ms = bs + 192;           // [64]
    float* rs = ms + 64;            // [64]

    const int tid = threadIdx.x;
    const int n = blockIdx.x >> 8;
    const int hw0 = (blockIdx.x & 255) << 6;
    const float* xin = x + (size_t)n * CH * HW + hw0;

    for (int idx = tid; idx < 64 * 64; idx += 256) {
        int c = idx >> 6, t = idx & 63;
        xs[c * 65 + t] = xin[(size_t)c * HW + t];
    }
    for (int idx = tid; idx < C3 * 64; idx += 256) {
        int o = idx >> 6, k = idx & 63;
        wT[k * 193 + o] = qkv_w[idx];
    }
    if (tid < C3) bs[tid] = qkv_b[tid];
    __syncthreads();

    const int warp = tid >> 5, lane = tid & 31;
    for (int j = 0; j < 8; j++) {
        int t = warp * 8 + j;
        float v0 = xs[(2 * lane) * 65 + t];
        float v1 = xs[(2 * lane + 1) * 65 + t];
        float s  = warp_sum(v0 + v1);
        float sq = warp_sum(v0 * v0 + v1 * v1);
        if (lane == 0) {
            float m = s * (1.0f / 64.0f);
            ms[t] = m;
            rs[t] = rsqrtf(sq * (1.0f / 64.0f) - m * m + 1e-5f);
        }
    }
    __syncthreads();
    for (int idx = tid; idx < 64 * 64; idx += 256) {
        int k = idx >> 6, t = idx & 63;
        xn[k * 68 + t] = (xs[k * 65 + t] - ms[t]) * rs[t] * ln_w[k] + ln_b[k];
    }
    __syncthreads();

    const int t0 = warp * 8;
    u64 acc[6][4];
#pragma unroll
    for (int jj = 0; jj < 6; jj++) {
        u64 b = pk2(bs[lane + 32 * jj]);
#pragma unroll
        for (int p = 0; p < 4; p++) acc[jj][p] = b;
    }
#pragma unroll 8
    for (int k = 0; k < 64; k++) {
        ulonglong2 xa = *(const ulonglong2*)&xn[k * 68 + t0];
        ulonglong2 xb = *(const ulonglong2*)&xn[k * 68 + t0 + 4];
#pragma unroll
        for (int jj = 0; jj < 6; jj++) {
            u64 w = pk2(wT[k * 193 + lane + 32 * jj]);
            fma2(acc[jj][0], xa.x, w);
            fma2(acc[jj][1], xa.y, w);
            fma2(acc[jj][2], xb.x, w);
            fma2(acc[jj][3], xb.y, w);
        }
    }
    float* qout = g_qkv + ((size_t)n * HW + hw0 + t0) * C3;
#pragma unroll
    for (int p = 0; p < 4; p++) {
#pragma unroll
        for (int jj = 0; jj < 6; jj++) {
            float2 v = up2(acc[jj][p]);
            if (jj < 2) { v.x *= 0.17677669529663687f; v.y *= 0.17677669529663687f; }
            qout[(size_t)(2 * p) * C3 + lane + 32 * jj]     = v.x;
            qout[(size_t)(2 * p + 1) * C3 + lane + 32 * jj] = v.y;
        }
    }
}

// ============================================================================
// K2: neighborhood attention (8x8 query tile per (n,head)).
// ============================================================================
__global__ __launch_bounds__(256, 2) void k_attn(const float* __restrict__ rpb)
{
    extern __shared__ float sm[];
    float* kx = sm;                  // [196][33]
    float* vx = kx + 196 * 33;       // [196][33]
    float* qx = vx + 196 * 33;       // [64][32]
    float* rp = qx + 64 * 32;        // [169]
    float* at = rp + 172;            // [8][52]

    const int tid = threadIdx.x, warp = tid >> 5, lane = tid & 31;
    const int b = blockIdx.x;
    const int nz = b >> 8, tile = b & 255;
    const int n = nz >> 1, z = nz & 1;
    const int h0 = (tile >> 4) << 3, w0 = (tile & 15) << 3;
    int r0 = h0 - 3; r0 = r0 < 0 ? 0 : (r0 > HT - 14 ? HT - 14 : r0);
    int c0 = w0 - 3; c0 = c0 < 0 ? 0 : (c0 > WD - 14 ? WD - 14 : c0);

    const float* qbase = g_qkv + (size_t)n * HW * C3;
    for (int rr = warp; rr < 196; rr += 8) {
        int pr = rr / 14, pc = rr - pr * 14;
        const float* p = qbase + (size_t)((r0 + pr) * WD + c0 + pc) * C3 + 64 + z * 32;
        kx[rr * 33 + lane] = p[lane];
        vx[rr * 33 + lane] = p[64 + lane];
    }
    for (int qi = warp; qi < 64; qi += 8) {
        int qh = h0 + (qi >> 3), qw = w0 + (qi & 7);
        qx[qi * 32 + lane] = qbase[(size_t)(qh * WD + qw) * C3 + z * 32 + lane];
    }
    if (tid < 169) rp[tid] = rpb[z * 169 + tid];
    __syncthreads();

    for (int j = 0; j < 8; j++) {
        const int qi = warp * 8 + j;
        const int qh = h0 + (qi >> 3), qw = w0 + (qi & 7);
        int sh = qh - 3; sh = sh < 0 ? 0 : (sh > HT - 7 ? HT - 7 : sh);
        int sw = qw - 3; sw = sw < 0 ? 0 : (sw > WD - 7 ? WD - 7 : sw);
        const int ph = sh - r0, pw = sw - c0;
        const int bh = qh - sh + 6, bw = qw - sw + 6;

        float4 q4[8];
#pragma unroll
        for (int d4 = 0; d4 < 8; d4++) q4[d4] = *(const float4*)&qx[qi * 32 + d4 * 4];

        float s1, s2 = -1e30f;
        {
            int e = lane;
            int i = e / 7, jn = e - i * 7;
            const float* kr = &kx[((ph + i) * 14 + pw + jn) * 33];
            float s = rp[(bh - i) * 13 + (bw - jn)];
#pragma unroll
            for (int d4 = 0; d4 < 8; d4++) {
                s = fmaf(q4[d4].x, kr[d4 * 4 + 0], s);
                s = fmaf(q4[d4].y, kr[d4 * 4 + 1], s);
                s = fmaf(q4[d4].z, kr[d4 * 4 + 2], s);
                s = fmaf(q4[d4].w, kr[d4 * 4 + 3], s);
            }
            s1 = s;
        }
        if (lane < 17) {
            int e = lane + 32;
            int i = e / 7, jn = e - i * 7;
            const float* kr = &kx[((ph + i) * 14 + pw + jn) * 33];
            float s = rp[(bh - i) * 13 + (bw - jn)];
#pragma unroll
            for (int d4 = 0; d4 < 8; d4++) {
                s = fmaf(q4[d4].x, kr[d4 * 4 + 0], s);
                s = fmaf(q4[d4].y, kr[d4 * 4 + 1], s);
                s = fmaf(q4[d4].z, kr[d4 * 4 + 2], s);
                s = fmaf(q4[d4].w, kr[d4 * 4 + 3], s);
            }
            s2 = s;
        }
        float mx = warp_max(fmaxf(s1, s2));
        float p1 = __expf(s1 - mx);
        float p2 = (lane < 17) ? __expf(s2 - mx) : 0.0f;
        float inv = 1.0f / warp_sum(p1 + p2);
        at[warp * 52 + lane] = p1 * inv;
        if (lane < 17) at[warp * 52 + 32 + lane] = p2 * inv;
        __syncwarp();

        float o = 0.0f;
#pragma unroll
        for (int e = 0; e < 49; e++) {
            int i = e / 7, jn = e - i * 7;
            o = fmaf(at[warp * 52 + e], vx[((ph + i) * 14 + pw + jn) * 33 + lane], o);
        }
        g_aout[(size_t)(n * HW + qh * WD + qw) * CH + z * 32 + lane] = o;
        __syncwarp();
    }
}

// ============================================================================
// K3 (fused): proj + residual + LN2 + FC1 + GELU + FC2 + residual + NCHW store
// 64 tokens / block, 256 threads, 2 CTAs/SM. One smem arena, 3 phases.
// ============================================================================
__global__ __launch_bounds__(256, 2) void k_mlp(
    const float* __restrict__ x, const float* __restrict__ proj_w,
    const float* __restrict__ proj_b, const float* __restrict__ fc1_w,
    const float* __restrict__ fc1_b, const float* __restrict__ fc2_b,
    const float* __restrict__ ln_w, const float* __restrict__ ln_b,
    float* __restrict__ out)
{
    extern __shared__ float sm[];
    // Phase A (proj)
    float* A_ao = sm;               // [64][68]  attn out, k-major
    float* A_xs = sm + 4352;        // [64][65]  shortcut ch-major
    float* A_wp = sm + 8512;        // [64][65]  proj wT        (ends 12672)
    // Phase B (fc1) — reuses A region
    float* B_xn = sm;               // [64][68]  normalized x2, k-major
    float* B_w1 = sm + 4352;        // [64][257] fc1 wT         (ends 20800)
    // Phase C (fc2) — reuses B region
    float* C_y1 = sm;               // [256][68] gelu(fc1)      (ends 17408)
    // persistent tail
    float* bs1 = sm + 20800;        // [256]
    float* bsp = bs1 + 256;         // [64]
    float* bs2 = bsp + 64;          // [64]
    float* os  = bs2 + 64;          // [64][68] output staging  (total 25536)

    const int tid = threadIdx.x, warp = tid >> 5, lane = tid & 31;
    const int n = blockIdx.x >> 8, hw0 = (blockIdx.x & 255) << 6;
    const int t0 = warp * 8;

    // ---- Phase A loads ----
    const float* ain = g_aout + ((size_t)n * HW + hw0) * CH;
    for (int idx = tid; idx < 64 * 64; idx += 256) {
        int t = idx >> 6, k = idx & 63;
        A_ao[k * 68 + t] = ain[(size_t)t * CH + k];
    }
    const float* xin = x + (size_t)n * CH * HW + hw0;
    for (int idx = tid; idx < 64 * 64; idx += 256) {
        int c = idx >> 6, t = idx & 63;
        A_xs[c * 65 + t] = xin[(size_t)c * HW + t];
    }
    for (int idx = tid; idx < 64 * 64; idx += 256) {
        int c = idx >> 6, k = idx & 63;
        A_wp[k * 65 + c] = proj_w[idx];
    }
    if (tid < C4) bs1[tid] = fc1_b[tid];
    if (tid >= 64 && tid < 128) bsp[tid - 64] = proj_b[tid - 64];
    if (tid >= 128 && tid < 192) bs2[tid - 128] = fc2_b[tid - 128];
    __syncthreads();

    // ---- proj GEMM ----
    u64 a0[4], a1[4];
    {
        u64 b0 = pk2(bsp[lane]), b1 = pk2(bsp[lane + 32]);
#pragma unroll
        for (int p = 0; p < 4; p++) { a0[p] = b0; a1[p] = b1; }
    }
#pragma unroll 8
    for (int k = 0; k < 64; k++) {
        ulonglong2 xa = *(const ulonglong2*)&A_ao[k * 68 + t0];
        ulonglong2 xb = *(const ulonglong2*)&A_ao[k * 68 + t0 + 4];
        u64 w0 = pk2(A_wp[k * 65 + lane]);
        u64 w1 = pk2(A_wp[k * 65 + lane + 32]);
        fma2(a0[0], xa.x, w0); fma2(a0[1], xa.y, w0);
        fma2(a0[2], xb.x, w0); fma2(a0[3], xb.y, w0);
        fma2(a1[0], xa.x, w1); fma2(a1[1], xa.y, w1);
        fma2(a1[2], xb.x, w1); fma2(a1[3], xb.y, w1);
    }
    // x2 = proj + shortcut, kept in registers (token t = t0+i, cols lane / lane+32)
    float x2c0[8], x2c1[8];
#pragma unroll
    for (int p = 0; p < 4; p++) {
        float2 v0 = up2(a0[p]), v1 = up2(a1[p]);
        x2c0[2 * p]     = v0.x + A_xs[lane * 65 + t0 + 2 * p];
        x2c0[2 * p + 1] = v0.y + A_xs[lane * 65 + t0 + 2 * p + 1];
        x2c1[2 * p]     = v1.x + A_xs[(lane + 32) * 65 + t0 + 2 * p];
        x2c1[2 * p + 1] = v1.y + A_xs[(lane + 32) * 65 + t0 + 2 * p + 1];
    }
    __syncthreads();   // phase A reads done; B region may be overwritten

    // ---- load fc1 weights ----
    for (int idx = tid; idx < C4 * 64; idx += 256) {
        int o = idx >> 6, k = idx & 63;
        B_w1[k * 257 + o] = fc1_w[idx];
    }
    // ---- LN2 stats in registers ----
    float lw0 = ln_w[lane], lb0 = ln_b[lane];
    float lw1 = ln_w[lane + 32], lb1 = ln_b[lane + 32];
#pragma unroll
    for (int t = 0; t < 8; t++) {
        float c0 = x2c0[t], c1 = x2c1[t];
        float s  = warp_sum(c0 + c1);
        float sq = warp_sum(c0 * c0 + c1 * c1);
        float m  = s * (1.0f / 64.0f);
        float r  = rsqrtf(sq * (1.0f / 64.0f) - m * m + 1e-5f);
        float n0 = (c0 - m) * r * lw0 + lb0;
        float n1 = (c1 - m) * r * lw1 + lb1;
        B_xn[lane * 68 + t0 + t]        = n0;
        B_xn[(lane + 32) * 68 + t0 + t] = n1;
    }
    __syncthreads();

    // ---- FC1 GEMM + GELU ----
    u64 acc[8][4];
#pragma unroll
    for (int jj = 0; jj < 8; jj++) {
        u64 b = pk2(bs1[lane + 32 * jj]);
#pragma unroll
        for (int p = 0; p < 4; p++) acc[jj][p] = b;
    }
#pragma unroll 2
    for (int k = 0; k < 64; k++) {
        ulonglong2 xa = *(const ulonglong2*)&B_xn[k * 68 + t0];
        ulonglong2 xb = *(const ulonglong2*)&B_xn[k * 68 + t0 + 4];
#pragma unroll
        for (int jj = 0; jj < 8; jj++) {
            u64 w = pk2(B_w1[k * 257 + lane + 32 * jj]);
            fma2(acc[jj][0], xa.x, w);
            fma2(acc[jj][1], xa.y, w);
            fma2(acc[jj][2], xb.x, w);
            fma2(acc[jj][3], xb.y, w);
        }
    }
    __syncthreads();   // phase B reads done; C region may be overwritten

#pragma unroll
    for (int jj = 0; jj < 8; jj++) {
#pragma unroll
        for (int p = 0; p < 4; p++) {
            float2 v = up2(acc[jj][p]);
            v.x = 0.5f * v.x * (1.0f + erff(v.x * 0.70710678118654752f));
            v.y = 0.5f * v.y * (1.0f + erff(v.y * 0.70710678118654752f));
            *(float2*)&C_y1[(lane + 32 * jj) * 68 + t0 + 2 * p] = v;
        }
    }
    __syncthreads();

    // ---- FC2 GEMM (weights: duplicated-packed LDG, L1-hot) ----
    u64 f0[4], f1[4];
    {
        u64 b0 = pk2(bs2[lane]), b1 = pk2(bs2[lane + 32]);
#pragma unroll
        for (int p = 0; p < 4; p++) { f0[p] = b0; f1[p] = b1; }
    }
#pragma unroll 4
    for (int k = 0; k < 256; k++) {
        ulonglong2 xa = *(const ulonglong2*)&C_y1[k * 68 + t0];
        ulonglong2 xb = *(const ulonglong2*)&C_y1[k * 68 + t0 + 4];
        u64 w0 = *(const u64*)&g_wt2d[k * 128 + 2 * lane];
        u64 w1 = *(const u64*)&g_wt2d[k * 128 + 2 * lane + 64];
        fma2(f0[0], xa.x, w0); fma2(f0[1], xa.y, w0);
        fma2(f0[2], xb.x, w0); fma2(f0[3], xb.y, w0);
        fma2(f1[0], xa.x, w1); fma2(f1[1], xa.y, w1);
        fma2(f1[2], xb.x, w1); fma2(f1[3], xb.y, w1);
    }
    // final residual + stage for transposed store
#pragma unroll
    for (int p = 0; p < 4; p++) {
        float2 v0 = up2(f0[p]), v1 = up2(f1[p]);
        v0.x += x2c0[2 * p]; v0.y += x2c0[2 * p + 1];
        v1.x += x2c1[2 * p]; v1.y += x2c1[2 * p + 1];
        *(float2*)&os[lane * 68 + t0 + 2 * p]        = v0;
        *(float2*)&os[(lane + 32) * 68 + t0 + 2 * p] = v1;
    }
    __syncthreads();
    float* oo = out + (size_t)n * CH * HW + hw0;
    for (int idx = tid; idx < 64 * 64; idx += 256) {
        int c = idx >> 6, t = idx & 63;
        oo[(size_t)c * HW + t] = os[c * 68 + t];
    }
}

// ---------------------------------------------------------------------------
extern "C" void kernel_launch(void* const* d_in, const int* in_sizes, int n_in,
                              void* d_out, int out_size)
{
    const float* x      = (const float*)d_in[0];
    const float* qkv_w  = (const float*)d_in[1];
    const float* qkv_b  = (const float*)d_in[2];
    const float* proj_w = (const float*)d_in[3];
    const float* proj_b = (const float*)d_in[4];
    const float* rpb    = (const float*)d_in[5];
    const float* ln1_w  = (const float*)d_in[6];
    const float* ln1_b  = (const float*)d_in[7];
    const float* ln2_w  = (const float*)d_in[8];
    const float* ln2_b  = (const float*)d_in[9];
    const float* fc1_w  = (const float*)d_in[10];
    const float* fc1_b  = (const float*)d_in[11];
    const float* fc2_w  = (const float*)d_in[12];
    const float* fc2_b  = (const float*)d_in[13];
    float* out = (float*)d_out;

    const int smB = (64 * 65 + 64 * 68 + 64 * 193 + 192 + 64 + 64) * 4;
    const int smC = (196 * 33 * 2 + 64 * 32 + 172 + 8 * 52) * 4;
    const int smM = 25536 * 4;

    cudaFuncSetAttribute(k_ln_qkv, cudaFuncAttributeMaxDynamicSharedMemorySize, smB);
    cudaFuncSetAttribute(k_attn,   cudaFuncAttributeMaxDynamicSharedMemorySize, smC);
    cudaFuncSetAttribute(k_mlp,    cudaFuncAttributeMaxDynamicSharedMemorySize, smM);

    k_wt<<<64, 256>>>(fc2_w);
    k_ln_qkv<<<512, 256, smB>>>(x, qkv_w, qkv_b, ln1_w, ln1_b);
    k_attn<<<1024, 256, smC>>>(rpb);
    k_mlp<<<512, 256, smM>>>(x, proj_w, proj_b, fc1_w, fc1_b, fc2_b,
                             ln2_w, ln2_b, out);
}